// round 2
// baseline (speedup 1.0000x reference)
#include <cuda_runtime.h>

// ---------------- problem constants ----------------
#define NU 40000
#define NI 20000
#define NN 60000            // NU + NI
#define DD 128
#define NE 320000
#define E2 640000           // directed edges (both directions)
#define NB 4096
#define SCAN_T 512
#define SCAN_NB ((NN + SCAN_T - 1) / SCAN_T)   // 118

// ---------------- device scratch (static, no allocs) ----------------
__device__ int   g_deg[NN];
__device__ float g_dinv[NN];
__device__ int   g_rs[NN];          // CSR row starts
__device__ int   g_cur[NN];         // fill cursors
__device__ int   g_col[E2];
__device__ float g_val[E2];
__device__ float g_xa[(size_t)NN * DD];
__device__ float g_xb[(size_t)NN * DD];
__device__ float g_acc[(size_t)NN * DD];
__device__ float g_loss;
__device__ int   g_part[128];

// ---------------- kernels ----------------
__global__ void k_zero() {
    int i = blockIdx.x * blockDim.x + threadIdx.x;
    if (i < NN) g_deg[i] = 0;
    if (i == 0) g_loss = 0.f;
}

__global__ void k_count(const int* __restrict__ au, const int* __restrict__ ai) {
    int i = blockIdx.x * blockDim.x + threadIdx.x;
    if (i >= NE) return;
    atomicAdd(&g_deg[au[i]], 1);
    atomicAdd(&g_deg[ai[i] + NU], 1);
}

__global__ void k_dinv() {
    int i = blockIdx.x * blockDim.x + threadIdx.x;
    if (i < NN) g_dinv[i] = rsqrtf((float)g_deg[i] + 1e-7f);
}

// ---- 3-kernel exclusive scan of g_deg -> g_rs, g_cur ----
__global__ void k_scan1() {
    __shared__ int sh[SCAN_T];
    int i = blockIdx.x * SCAN_T + threadIdx.x;
    sh[threadIdx.x] = (i < NN) ? g_deg[i] : 0;
    __syncthreads();
    for (int s = SCAN_T / 2; s > 0; s >>= 1) {
        if (threadIdx.x < s) sh[threadIdx.x] += sh[threadIdx.x + s];
        __syncthreads();
    }
    if (threadIdx.x == 0) g_part[blockIdx.x] = sh[0];
}

__global__ void k_scan2() {
    __shared__ int sh[128];
    int t = threadIdx.x;
    int v = (t < SCAN_NB) ? g_part[t] : 0;
    sh[t] = v;
    __syncthreads();
    for (int off = 1; off < 128; off <<= 1) {
        int u = (t >= off) ? sh[t - off] : 0;
        __syncthreads();
        sh[t] += u;
        __syncthreads();
    }
    if (t < SCAN_NB) g_part[t] = sh[t] - v;   // exclusive
}

__global__ void k_scan3() {
    __shared__ int sh[SCAN_T];
    int i = blockIdx.x * SCAN_T + threadIdx.x;
    int v = (i < NN) ? g_deg[i] : 0;
    sh[threadIdx.x] = v;
    __syncthreads();
    for (int off = 1; off < SCAN_T; off <<= 1) {
        int u = (threadIdx.x >= off) ? sh[threadIdx.x - off] : 0;
        __syncthreads();
        sh[threadIdx.x] += u;
        __syncthreads();
    }
    if (i < NN) {
        int ex = sh[threadIdx.x] - v + g_part[blockIdx.x];
        g_rs[i]  = ex;
        g_cur[i] = ex;
    }
}

__global__ void k_fill(const int* __restrict__ au, const int* __restrict__ ai) {
    int i = blockIdx.x * blockDim.x + threadIdx.x;
    if (i >= NE) return;
    int u  = au[i];
    int it = ai[i] + NU;
    float v = g_dinv[u] * g_dinv[it];
    int pu = atomicAdd(&g_cur[u], 1);
    g_col[pu] = it;  g_val[pu] = v;
    int pi = atomicAdd(&g_cur[it], 1);
    g_col[pi] = u;   g_val[pi] = v;
}

__global__ void k_init(const float4* __restrict__ ue, const float4* __restrict__ ie) {
    int i = blockIdx.x * blockDim.x + threadIdx.x;
    const int TOT = NN * DD / 4;
    if (i >= TOT) return;
    float4 v = (i < NU * DD / 4) ? __ldg(&ue[i]) : __ldg(&ie[i - NU * DD / 4]);
    ((float4*)g_xa)[i]  = v;
    ((float4*)g_acc)[i] = v;
}

// One warp per row. lane owns a float4 slice of D=128.
__global__ __launch_bounds__(256) void k_spmm(int dir) {
    const float* __restrict__ x  = dir ? g_xb : g_xa;
    float*       __restrict__ xn = dir ? g_xa : g_xb;

    int gw   = (blockIdx.x * blockDim.x + threadIdx.x) >> 5;
    int lane = threadIdx.x & 31;
    if (gw >= NN) return;

    int start = g_rs[gw];
    int n     = g_deg[gw];
    int end   = start + n;

    const float4* __restrict__ x4 = (const float4*)x;
    float4 s = make_float4(0.f, 0.f, 0.f, 0.f);

    int e = start;
    for (; e + 4 <= end; e += 4) {
        int   c0 = g_col[e],     c1 = g_col[e + 1],
              c2 = g_col[e + 2], c3 = g_col[e + 3];
        float v0 = g_val[e],     v1 = g_val[e + 1],
              v2 = g_val[e + 2], v3 = g_val[e + 3];
        float4 a0 = __ldg(&x4[(size_t)c0 * 32 + lane]);
        float4 a1 = __ldg(&x4[(size_t)c1 * 32 + lane]);
        float4 a2 = __ldg(&x4[(size_t)c2 * 32 + lane]);
        float4 a3 = __ldg(&x4[(size_t)c3 * 32 + lane]);
        s.x += v0 * a0.x; s.y += v0 * a0.y; s.z += v0 * a0.z; s.w += v0 * a0.w;
        s.x += v1 * a1.x; s.y += v1 * a1.y; s.z += v1 * a1.z; s.w += v1 * a1.w;
        s.x += v2 * a2.x; s.y += v2 * a2.y; s.z += v2 * a2.z; s.w += v2 * a2.w;
        s.x += v3 * a3.x; s.y += v3 * a3.y; s.z += v3 * a3.z; s.w += v3 * a3.w;
    }
    for (; e < end; e++) {
        int   c = g_col[e];
        float v = g_val[e];
        float4 a = __ldg(&x4[(size_t)c * 32 + lane]);
        s.x += v * a.x; s.y += v * a.y; s.z += v * a.z; s.w += v * a.w;
    }

    size_t o = (size_t)gw * 32 + lane;
    ((float4*)xn)[o] = s;
    float4* acc4 = (float4*)g_acc;
    float4 a = acc4[o];
    a.x += s.x; a.y += s.y; a.z += s.z; a.w += s.w;
    acc4[o] = a;
}

// One warp per batch element: diff = tu·(pi-ni)/16; loss term = softplus(-diff)
__global__ void k_score(const int* __restrict__ user,
                        const int* __restrict__ pos,
                        const int* __restrict__ neg) {
    int gw   = (blockIdx.x * blockDim.x + threadIdx.x) >> 5;
    int lane = threadIdx.x & 31;
    if (gw >= NB) return;

    const float4* __restrict__ a4 = (const float4*)g_acc;
    size_t u = (size_t)user[gw] * 32 + lane;
    size_t p = (size_t)(NU + pos[gw] - 1) * 32 + lane;
    size_t q = (size_t)(NU + neg[gw] - 1) * 32 + lane;

    float4 tu = __ldg(&a4[u]);
    float4 pi = __ldg(&a4[p]);
    float4 ni = __ldg(&a4[q]);

    float s = tu.x * (pi.x - ni.x) + tu.y * (pi.y - ni.y)
            + tu.z * (pi.z - ni.z) + tu.w * (pi.w - ni.w);
    #pragma unroll
    for (int off = 16; off; off >>= 1)
        s += __shfl_xor_sync(0xffffffffu, s, off);

    if (lane == 0) {
        float diff = s * (1.f / 16.f);          // (acc/4)·(acc/4) scaling
        float t = -diff;                        // softplus(-diff) = -log sigmoid(diff)
        float term = fmaxf(t, 0.f) + log1pf(expf(-fabsf(t)));
        atomicAdd(&g_loss, term);
    }
}

__global__ void k_fin(float* out) {
    out[0] = g_loss * (1.f / (float)NB);
}

// ---------------- launch ----------------
extern "C" void kernel_launch(void* const* d_in, const int* in_sizes, int n_in,
                              void* d_out, int out_size) {
    const float* ue  = (const float*)d_in[0];
    const float* ie  = (const float*)d_in[1];
    const int*   au  = (const int*)d_in[2];
    const int*   ai  = (const int*)d_in[3];
    const int*   usr = (const int*)d_in[4];
    const int*   pos = (const int*)d_in[5];
    const int*   neg = (const int*)d_in[6];
    float*       out = (float*)d_out;

    k_zero <<<(NN + 255) / 256, 256>>>();
    k_count<<<(NE + 255) / 256, 256>>>(au, ai);
    k_dinv <<<(NN + 255) / 256, 256>>>();
    k_scan1<<<SCAN_NB, SCAN_T>>>();
    k_scan2<<<1, 128>>>();
    k_scan3<<<SCAN_NB, SCAN_T>>>();
    k_fill <<<(NE + 255) / 256, 256>>>(au, ai);
    k_init <<<(NN * DD / 4 + 255) / 256, 256>>>((const float4*)ue, (const float4*)ie);

    const int SPMM_BLOCKS = (NN * 32 + 255) / 256;   // one warp per row
    k_spmm<<<SPMM_BLOCKS, 256>>>(0);   // xa -> xb
    k_spmm<<<SPMM_BLOCKS, 256>>>(1);   // xb -> xa
    k_spmm<<<SPMM_BLOCKS, 256>>>(0);   // xa -> xb

    k_score<<<(NB * 32 + 255) / 256, 256>>>(usr, pos, neg);
    k_fin  <<<1, 1>>>(out);
}

// round 3
// speedup vs baseline: 1.3527x; 1.3527x over previous
#include <cuda_runtime.h>
#include <cuda_fp16.h>

// ---------------- problem constants ----------------
#define NU 40000
#define NI 20000
#define NN 60000            // NU + NI
#define DD 128
#define NE 320000
#define E2 640000           // directed edges (both directions)
#define NB 4096
#define SCAN_T 512
#define SCAN_NB ((NN + SCAN_T - 1) / SCAN_T)   // 118

// ---------------- device scratch (static, no allocs) ----------------
__device__ int   g_deg[NN];
__device__ float g_dinv[NN];
__device__ int   g_rs[NN];          // CSR row starts
__device__ int   g_cur[NN];         // fill cursors
__device__ int   g_col[E2];
__device__ float g_val[E2];
// fp16 embeddings: one row = 128 halves = 32 uint2 (8B per lane)
__device__ uint2 g_x0[(size_t)NN * 32];
__device__ uint2 g_x1[(size_t)NN * 32];
__device__ uint2 g_x2[(size_t)NN * 32];
__device__ uint2 g_x3[(size_t)NN * 32];
__device__ float g_loss;
__device__ int   g_part[128];

// ---------------- init: convert inputs to fp16 x0, zero deg & loss ----------------
__global__ void k_init(const float4* __restrict__ ue, const float4* __restrict__ ie) {
    int i = blockIdx.x * blockDim.x + threadIdx.x;   // one float4 (=4 dims) per thread
    const int TOT = NN * DD / 4;                     // 1.92M
    if (i < NN) g_deg[i] = 0;
    if (i == 0) g_loss = 0.f;
    if (i >= TOT) return;
    float4 v = (i < NU * DD / 4) ? __ldg(&ue[i]) : __ldg(&ie[i - NU * DD / 4]);
    __half2 h0 = __float22half2_rn(make_float2(v.x, v.y));
    __half2 h1 = __float22half2_rn(make_float2(v.z, v.w));
    uint2 o;
    o.x = *(unsigned int*)&h0;
    o.y = *(unsigned int*)&h1;
    g_x0[i] = o;
}

__global__ void k_count(const int* __restrict__ au, const int* __restrict__ ai) {
    int i = blockIdx.x * blockDim.x + threadIdx.x;
    if (i >= NE) return;
    atomicAdd(&g_deg[au[i]], 1);
    atomicAdd(&g_deg[ai[i] + NU], 1);
}

// ---- scan of g_deg -> g_rs/g_cur; scan1 also emits dinv ----
__global__ void k_scan1() {
    __shared__ int sh[SCAN_T];
    int i = blockIdx.x * SCAN_T + threadIdx.x;
    int d = (i < NN) ? g_deg[i] : 0;
    if (i < NN) g_dinv[i] = rsqrtf((float)d + 1e-7f);
    sh[threadIdx.x] = d;
    __syncthreads();
    for (int s = SCAN_T / 2; s > 0; s >>= 1) {
        if (threadIdx.x < s) sh[threadIdx.x] += sh[threadIdx.x + s];
        __syncthreads();
    }
    if (threadIdx.x == 0) g_part[blockIdx.x] = sh[0];
}

__global__ void k_scan2() {
    __shared__ int sh[128];
    int t = threadIdx.x;
    int v = (t < SCAN_NB) ? g_part[t] : 0;
    sh[t] = v;
    __syncthreads();
    for (int off = 1; off < 128; off <<= 1) {
        int u = (t >= off) ? sh[t - off] : 0;
        __syncthreads();
        sh[t] += u;
        __syncthreads();
    }
    if (t < SCAN_NB) g_part[t] = sh[t] - v;   // exclusive
}

__global__ void k_scan3() {
    __shared__ int sh[SCAN_T];
    int i = blockIdx.x * SCAN_T + threadIdx.x;
    int v = (i < NN) ? g_deg[i] : 0;
    sh[threadIdx.x] = v;
    __syncthreads();
    for (int off = 1; off < SCAN_T; off <<= 1) {
        int u = (threadIdx.x >= off) ? sh[threadIdx.x - off] : 0;
        __syncthreads();
        sh[threadIdx.x] += u;
        __syncthreads();
    }
    if (i < NN) {
        int ex = sh[threadIdx.x] - v + g_part[blockIdx.x];
        g_rs[i]  = ex;
        g_cur[i] = ex;
    }
}

__global__ void k_fill(const int* __restrict__ au, const int* __restrict__ ai) {
    int i = blockIdx.x * blockDim.x + threadIdx.x;
    if (i >= NE) return;
    int u  = au[i];
    int it = ai[i] + NU;
    float v = g_dinv[u] * g_dinv[it];
    int pu = atomicAdd(&g_cur[u], 1);
    g_col[pu] = it;  g_val[pu] = v;
    int pi = atomicAdd(&g_cur[it], 1);
    g_col[pi] = u;   g_val[pi] = v;
}

// ---------------- SpMM: one warp per row, fp16 gathers, fp32 accumulate ----------------
__device__ __forceinline__ void edge_fma(float2& s0, float2& s1, float v, uint2 w) {
    float2 a = __half22float2(*(__half2*)&w.x);
    float2 b = __half22float2(*(__half2*)&w.y);
    s0.x += v * a.x; s0.y += v * a.y;
    s1.x += v * b.x; s1.y += v * b.y;
}

__global__ __launch_bounds__(256) void k_spmm(int stage) {
    const uint2* __restrict__ x  = (stage == 0) ? g_x0 : (stage == 1) ? g_x1 : g_x2;
    uint2*       __restrict__ xn = (stage == 0) ? g_x1 : (stage == 1) ? g_x2 : g_x3;

    int gw   = (blockIdx.x * blockDim.x + threadIdx.x) >> 5;
    int lane = threadIdx.x & 31;
    if (gw >= NN) return;

    int start = g_rs[gw];
    int end   = start + g_deg[gw];

    float2 s0 = make_float2(0.f, 0.f);
    float2 s1 = make_float2(0.f, 0.f);

    int e = start;
    for (; e + 4 <= end; e += 4) {
        int   c0 = g_col[e],     c1 = g_col[e + 1],
              c2 = g_col[e + 2], c3 = g_col[e + 3];
        float v0 = g_val[e],     v1 = g_val[e + 1],
              v2 = g_val[e + 2], v3 = g_val[e + 3];
        uint2 w0 = __ldg(&x[(size_t)c0 * 32 + lane]);
        uint2 w1 = __ldg(&x[(size_t)c1 * 32 + lane]);
        uint2 w2 = __ldg(&x[(size_t)c2 * 32 + lane]);
        uint2 w3 = __ldg(&x[(size_t)c3 * 32 + lane]);
        edge_fma(s0, s1, v0, w0);
        edge_fma(s0, s1, v1, w1);
        edge_fma(s0, s1, v2, w2);
        edge_fma(s0, s1, v3, w3);
    }
    for (; e < end; e++) {
        int   c = g_col[e];
        float v = g_val[e];
        uint2 w = __ldg(&x[(size_t)c * 32 + lane]);
        edge_fma(s0, s1, v, w);
    }

    __half2 h0 = __float22half2_rn(s0);
    __half2 h1 = __float22half2_rn(s1);
    uint2 o;
    o.x = *(unsigned int*)&h0;
    o.y = *(unsigned int*)&h1;
    xn[(size_t)gw * 32 + lane] = o;
}

// ---------------- score: layer-sum gathered on demand ----------------
__device__ __forceinline__ float4 row_layersum(const float4* __restrict__ base4,
                                               int brow, int nrow, int lane) {
    float4 r = __ldg(&base4[(size_t)brow * 32 + lane]);   // x0 in fp32 from inputs
    size_t o = (size_t)nrow * 32 + lane;
    uint2 w1 = __ldg(&g_x1[o]);
    uint2 w2 = __ldg(&g_x2[o]);
    uint2 w3 = __ldg(&g_x3[o]);
    float2 a, b;
    a = __half22float2(*(__half2*)&w1.x); b = __half22float2(*(__half2*)&w1.y);
    r.x += a.x; r.y += a.y; r.z += b.x; r.w += b.y;
    a = __half22float2(*(__half2*)&w2.x); b = __half22float2(*(__half2*)&w2.y);
    r.x += a.x; r.y += a.y; r.z += b.x; r.w += b.y;
    a = __half22float2(*(__half2*)&w3.x); b = __half22float2(*(__half2*)&w3.y);
    r.x += a.x; r.y += a.y; r.z += b.x; r.w += b.y;
    return r;
}

__global__ void k_score(const float4* __restrict__ ue4,
                        const float4* __restrict__ ie4,
                        const int* __restrict__ user,
                        const int* __restrict__ pos,
                        const int* __restrict__ neg) {
    int gw   = (blockIdx.x * blockDim.x + threadIdx.x) >> 5;
    int lane = threadIdx.x & 31;
    if (gw >= NB) return;

    int u = user[gw];
    int p = pos[gw] - 1;
    int q = neg[gw] - 1;

    float4 tu = row_layersum(ue4, u, u, lane);
    float4 pi = row_layersum(ie4, p, NU + p, lane);
    float4 ni = row_layersum(ie4, q, NU + q, lane);

    float s = tu.x * (pi.x - ni.x) + tu.y * (pi.y - ni.y)
            + tu.z * (pi.z - ni.z) + tu.w * (pi.w - ni.w);
    #pragma unroll
    for (int off = 16; off; off >>= 1)
        s += __shfl_xor_sync(0xffffffffu, s, off);

    if (lane == 0) {
        float diff = s * (1.f / 16.f);          // ((sum)/4)·((sum)/4)
        float t = -diff;                        // softplus(-diff) = -log sigmoid(diff)
        float term = fmaxf(t, 0.f) + log1pf(expf(-fabsf(t)));
        atomicAdd(&g_loss, term);
    }
}

__global__ void k_fin(float* out) {
    out[0] = g_loss * (1.f / (float)NB);
}

// ---------------- launch ----------------
extern "C" void kernel_launch(void* const* d_in, const int* in_sizes, int n_in,
                              void* d_out, int out_size) {
    const float* ue  = (const float*)d_in[0];
    const float* ie  = (const float*)d_in[1];
    const int*   au  = (const int*)d_in[2];
    const int*   ai  = (const int*)d_in[3];
    const int*   usr = (const int*)d_in[4];
    const int*   pos = (const int*)d_in[5];
    const int*   neg = (const int*)d_in[6];
    float*       out = (float*)d_out;

    k_init <<<(NN * DD / 4 + 255) / 256, 256>>>((const float4*)ue, (const float4*)ie);
    k_count<<<(NE + 255) / 256, 256>>>(au, ai);
    k_scan1<<<SCAN_NB, SCAN_T>>>();
    k_scan2<<<1, 128>>>();
    k_scan3<<<SCAN_NB, SCAN_T>>>();
    k_fill <<<(NE + 255) / 256, 256>>>(au, ai);

    const int SPMM_BLOCKS = (NN * 32 + 255) / 256;   // one warp per row
    k_spmm<<<SPMM_BLOCKS, 256>>>(0);   // x0 -> x1
    k_spmm<<<SPMM_BLOCKS, 256>>>(1);   // x1 -> x2
    k_spmm<<<SPMM_BLOCKS, 256>>>(2);   // x2 -> x3

    k_score<<<(NB * 32 + 255) / 256, 256>>>((const float4*)ue, (const float4*)ie,
                                            usr, pos, neg);
    k_fin  <<<1, 1>>>(out);
}